// round 2
// baseline (speedup 1.0000x reference)
#include <cuda_runtime.h>
#include <math.h>
#include <stddef.h>

#define T_TOK 4096
#define DM    1024
#define FF    4096
#define NE    8
#define NA    (T_TOK*2)

// -------- device scratch (static, allocation-free) --------
__device__ int   g_count[NE];
__device__ int   g_offset[NE+1];
__device__ int   g_tok[NA];      // token id per assignment, grouped by expert
__device__ float g_wt[NA];       // combine weight per assignment
__device__ int   g_tok_e[NA];    // per-token top2 experts (token-major)
__device__ float g_tok_w[NA];    // per-token top2 weights (token-major)
__device__ float g_probs[T_TOK*NE];
__device__ float g_h[(size_t)NA*FF];   // 128 MB fp32 hidden scratch

// -------- zero out + counters --------
__global__ void k_zero(float* out){
    size_t n = (size_t)T_TOK*DM;
    size_t stride = (size_t)gridDim.x*blockDim.x;
    for (size_t i = (size_t)blockIdx.x*blockDim.x + threadIdx.x; i < n; i += stride)
        out[i] = 0.0f;
    if (blockIdx.x == 0 && threadIdx.x < NE) g_count[threadIdx.x] = 0;
}

// -------- router: one warp per token --------
__global__ void k_router(const float* __restrict__ x,
                         const float* __restrict__ rw,
                         const float* __restrict__ rb){
    int t    = blockIdx.x*8 + (threadIdx.x>>5);
    int lane = threadIdx.x & 31;
    if (t >= T_TOK) return;

    float acc[NE];
    #pragma unroll
    for (int e=0;e<NE;e++) acc[e]=0.0f;

    const float4* x4 = (const float4*)(x + (size_t)t*DM);
    for (int k4 = lane; k4 < DM/4; k4 += 32){
        float4 xv = x4[k4];
        int k = k4*4;
        #pragma unroll
        for (int e=0;e<NE;e++){
            acc[e] += xv.x*rw[(k+0)*NE+e] + xv.y*rw[(k+1)*NE+e]
                    + xv.z*rw[(k+2)*NE+e] + xv.w*rw[(k+3)*NE+e];
        }
    }
    #pragma unroll
    for (int off=16; off>0; off>>=1)
        #pragma unroll
        for (int e=0;e<NE;e++)
            acc[e] += __shfl_down_sync(0xFFFFFFFFu, acc[e], off);

    if (lane == 0){
        float p[NE];
        float m = -1e30f;
        #pragma unroll
        for (int e=0;e<NE;e++){ p[e] = acc[e] + rb[e]; m = fmaxf(m, p[e]); }
        float s = 0.0f;
        #pragma unroll
        for (int e=0;e<NE;e++){ p[e] = expf(p[e]-m); s += p[e]; }
        float inv_s = 1.0f/s;
        #pragma unroll
        for (int e=0;e<NE;e++){ p[e] *= inv_s; g_probs[t*NE+e] = p[e]; }

        int i0 = 0;
        #pragma unroll
        for (int e=1;e<NE;e++) if (p[e] > p[i0]) i0 = e;
        int i1 = (i0==0) ? 1 : 0;
        #pragma unroll
        for (int e=0;e<NE;e++) if (e != i0 && p[e] > p[i1]) i1 = e;

        float inv = 1.0f/(p[i0]+p[i1]);
        g_tok_e[t*2+0] = i0; g_tok_w[t*2+0] = p[i0]*inv;
        g_tok_e[t*2+1] = i1; g_tok_w[t*2+1] = p[i1]*inv;
        atomicAdd(&g_count[i0], 1);
        atomicAdd(&g_count[i1], 1);
    }
}

// -------- exclusive scan over 8 counts --------
__global__ void k_scan(){
    int s = 0;
    for (int e=0;e<NE;e++){ g_offset[e] = s; s += g_count[e]; g_count[e] = 0; }
    g_offset[NE] = s;
}

// -------- scatter assignments into expert-grouped lists --------
__global__ void k_scatter(){
    int i = blockIdx.x*blockDim.x + threadIdx.x;
    if (i >= NA) return;
    int e   = g_tok_e[i];
    int pos = g_offset[e] + atomicAdd(&g_count[e], 1);
    g_tok[pos] = i >> 1;
    g_wt[pos]  = g_tok_w[i];
}

// -------- grouped GEMM1: h = gelu(x_sel @ w1[e] + b1[e]) --------
__global__ __launch_bounds__(256, 2)
void k_gemm1(const float* __restrict__ x,
             const float* __restrict__ w1,
             const float* __restrict__ b1){
    const int e = blockIdx.z, mt = blockIdx.y, nt = blockIdx.x;
    const int off = g_offset[e];
    const int ne  = g_offset[e+1] - off;
    if (mt*128 >= ne) return;

    __shared__ float As[16][128];
    __shared__ float Bs[16][128];

    const float* __restrict__ B = w1 + (size_t)e*DM*FF + nt*128;
    const int tid  = threadIdx.x;
    const int arow = tid >> 2;        // 0..63
    const int ak   = (tid & 3) << 2;  // 0,4,8,12
    const int bk   = tid >> 4;        // 0..15
    const int bn   = (tid & 15) << 3; // 0..120
    const int tm   = tid >> 4, tn = tid & 15;

    const float* aptr[2];
    #pragma unroll
    for (int j=0;j<2;j++){
        int m = arow + j*64;
        int g = off + mt*128 + m;
        aptr[j] = (mt*128 + m < ne) ? (x + (size_t)g_tok[g]*DM) : (const float*)0;
    }

    float acc[8][8];
    #pragma unroll
    for (int i=0;i<8;i++)
        #pragma unroll
        for (int j=0;j<8;j++) acc[i][j]=0.0f;

    for (int k0=0;k0<DM;k0+=16){
        #pragma unroll
        for (int j=0;j<2;j++){
            float4 v = make_float4(0,0,0,0);
            if (aptr[j]) v = *(const float4*)(aptr[j]+k0+ak);
            As[ak+0][arow+j*64]=v.x; As[ak+1][arow+j*64]=v.y;
            As[ak+2][arow+j*64]=v.z; As[ak+3][arow+j*64]=v.w;
        }
        #pragma unroll
        for (int j=0;j<2;j++){
            float4 v = *(const float4*)(B + (size_t)(k0+bk)*FF + bn + j*4);
            *(float4*)&Bs[bk][bn+j*4] = v;
        }
        __syncthreads();
        #pragma unroll
        for (int kk=0;kk<16;kk++){
            float a[8], b[8];
            *(float4*)(a)   = *(const float4*)&As[kk][tm*8];
            *(float4*)(a+4) = *(const float4*)&As[kk][tm*8+4];
            *(float4*)(b)   = *(const float4*)&Bs[kk][tn*8];
            *(float4*)(b+4) = *(const float4*)&Bs[kk][tn*8+4];
            #pragma unroll
            for (int i=0;i<8;i++)
                #pragma unroll
                for (int j=0;j<8;j++)
                    acc[i][j] += a[i]*b[j];
        }
        __syncthreads();
    }

    #pragma unroll
    for (int i=0;i<8;i++){
        int m = tm*8 + i;
        if (mt*128 + m >= ne) continue;
        size_t row = (size_t)(off + mt*128 + m);
        #pragma unroll
        for (int j=0;j<8;j++){
            int n = nt*128 + tn*8 + j;
            float v = acc[i][j] + b1[e*FF + n];
            v = 0.5f*v*(1.0f + erff(v*0.70710678118654752440f));
            g_h[row*FF + n] = v;
        }
    }
}

// -------- grouped GEMM2: out += wt * (h @ w2[e] + b2[e]) --------
__global__ __launch_bounds__(256, 2)
void k_gemm2(const float* __restrict__ w2,
             const float* __restrict__ b2,
             float* __restrict__ out){
    const int e = blockIdx.z, mt = blockIdx.y, nt = blockIdx.x;
    const int off = g_offset[e];
    const int ne  = g_offset[e+1] - off;
    if (mt*128 >= ne) return;

    __shared__ float As[16][128];
    __shared__ float Bs[16][128];

    const float* __restrict__ B = w2 + (size_t)e*FF*DM + nt*128;
    const int tid  = threadIdx.x;
    const int arow = tid >> 2;
    const int ak   = (tid & 3) << 2;
    const int bk   = tid >> 4;
    const int bn   = (tid & 15) << 3;
    const int tm   = tid >> 4, tn = tid & 15;

    const float* aptr[2];
    #pragma unroll
    for (int j=0;j<2;j++){
        int m = arow + j*64;
        aptr[j] = (mt*128 + m < ne) ? (g_h + (size_t)(off + mt*128 + m)*FF) : (const float*)0;
    }

    float acc[8][8];
    #pragma unroll
    for (int i=0;i<8;i++)
        #pragma unroll
        for (int j=0;j<8;j++) acc[i][j]=0.0f;

    for (int k0=0;k0<FF;k0+=16){
        #pragma unroll
        for (int j=0;j<2;j++){
            float4 v = make_float4(0,0,0,0);
            if (aptr[j]) v = *(const float4*)(aptr[j]+k0+ak);
            As[ak+0][arow+j*64]=v.x; As[ak+1][arow+j*64]=v.y;
            As[ak+2][arow+j*64]=v.z; As[ak+3][arow+j*64]=v.w;
        }
        #pragma unroll
        for (int j=0;j<2;j++){
            float4 v = *(const float4*)(B + (size_t)(k0+bk)*DM + bn + j*4);
            *(float4*)&Bs[bk][bn+j*4] = v;
        }
        __syncthreads();
        #pragma unroll
        for (int kk=0;kk<16;kk++){
            float a[8], b[8];
            *(float4*)(a)   = *(const float4*)&As[kk][tm*8];
            *(float4*)(a+4) = *(const float4*)&As[kk][tm*8+4];
            *(float4*)(b)   = *(const float4*)&Bs[kk][tn*8];
            *(float4*)(b+4) = *(const float4*)&Bs[kk][tn*8+4];
            #pragma unroll
            for (int i=0;i<8;i++)
                #pragma unroll
                for (int j=0;j<8;j++)
                    acc[i][j] += a[i]*b[j];
        }
        __syncthreads();
    }

    #pragma unroll
    for (int i=0;i<8;i++){
        int m = tm*8 + i;
        if (mt*128 + m >= ne) continue;
        int g   = off + mt*128 + m;
        int tok = g_tok[g];
        float wt = g_wt[g];
        #pragma unroll
        for (int j=0;j<8;j++){
            int n = nt*128 + tn*8 + j;
            float y = acc[i][j] + b2[e*DM + n];
            atomicAdd(out + (size_t)tok*DM + n, wt*y);
        }
    }
}

// -------- aux loss: var(mean_probs, ddof=1) --------
__global__ void k_aux(float* out, int out_size){
    __shared__ float red[256];
    __shared__ float meanp[NE];
    int tid = threadIdx.x;
    float s[NE];
    #pragma unroll
    for (int e=0;e<NE;e++) s[e]=0.0f;
    for (int t = tid; t < T_TOK; t += 256)
        #pragma unroll
        for (int e=0;e<NE;e++) s[e] += g_probs[t*NE+e];

    for (int e=0;e<NE;e++){
        red[tid] = s[e]; __syncthreads();
        for (int o=128;o>0;o>>=1){
            if (tid < o) red[tid] += red[tid+o];
            __syncthreads();
        }
        if (tid == 0) meanp[e] = red[0]/(float)T_TOK;
        __syncthreads();
    }
    if (tid == 0){
        float mu = 0.0f;
        #pragma unroll
        for (int e=0;e<NE;e++) mu += meanp[e];
        mu /= (float)NE;
        float v = 0.0f;
        #pragma unroll
        for (int e=0;e<NE;e++){ float d = meanp[e]-mu; v += d*d; }
        v /= (float)(NE-1);
        if (out_size > T_TOK*DM) out[T_TOK*DM] = v;
    }
}

extern "C" void kernel_launch(void* const* d_in, const int* in_sizes, int n_in,
                              void* d_out, int out_size){
    const float* x  = (const float*)d_in[0];
    const float* rw = (const float*)d_in[1];
    const float* rb = (const float*)d_in[2];
    const float* w1 = (const float*)d_in[3];
    const float* b1 = (const float*)d_in[4];
    const float* w2 = (const float*)d_in[5];
    const float* b2 = (const float*)d_in[6];
    float* out = (float*)d_out;

    k_zero   <<<1024, 256>>>(out);
    k_router <<<T_TOK/8, 256>>>(x, rw, rb);
    k_scan   <<<1, 1>>>();
    k_scatter<<<NA/256, 256>>>();
    k_gemm1  <<<dim3(FF/128, 64, NE), 256>>>(x, w1, b1);
    k_gemm2  <<<dim3(DM/128, 64, NE), 256>>>(w2, b2, out);
    k_aux    <<<1, 256>>>(out, out_size);
}

// round 4
// speedup vs baseline: 2.9624x; 2.9624x over previous
#include <cuda_runtime.h>
#include <math.h>
#include <stddef.h>
#include <stdint.h>

#define T_TOK 4096
#define DM    1024
#define FF    4096
#define NE    8
#define NA    (T_TOK*2)

// -------- device scratch (static, allocation-free) --------
__device__ int   g_count[NE];
__device__ int   g_offset[NE+1];
__device__ int   g_tok[NA];      // token id per assignment, grouped by expert
__device__ float g_wt[NA];       // combine weight per assignment
__device__ int   g_tok_e[NA];    // per-token top2 experts (token-major)
__device__ float g_tok_w[NA];    // per-token top2 weights (token-major)
__device__ float g_probs[T_TOK*NE];
__device__ float g_h[(size_t)NA*FF];   // 128 MB fp32 hidden scratch

// round fp32 -> tf32 (RNA) in-place on bits
__device__ __forceinline__ float f2tf32(float f){
    uint32_t b = __float_as_uint(f);
    asm("cvt.rna.tf32.f32 %0, %0;" : "+r"(b));
    return __uint_as_float(b);
}

// -------- zero out + counters --------
__global__ void k_zero(float* out){
    size_t n = (size_t)T_TOK*DM;
    size_t stride = (size_t)gridDim.x*blockDim.x;
    for (size_t i = (size_t)blockIdx.x*blockDim.x + threadIdx.x; i < n; i += stride)
        out[i] = 0.0f;
    if (blockIdx.x == 0 && threadIdx.x < NE) g_count[threadIdx.x] = 0;
}

// -------- router: one warp per token --------
__global__ void k_router(const float* __restrict__ x,
                         const float* __restrict__ rw,
                         const float* __restrict__ rb){
    int t    = blockIdx.x*8 + (threadIdx.x>>5);
    int lane = threadIdx.x & 31;
    if (t >= T_TOK) return;

    float acc[NE];
    #pragma unroll
    for (int e=0;e<NE;e++) acc[e]=0.0f;

    const float4* x4 = (const float4*)(x + (size_t)t*DM);
    for (int k4 = lane; k4 < DM/4; k4 += 32){
        float4 xv = x4[k4];
        int k = k4*4;
        #pragma unroll
        for (int e=0;e<NE;e++){
            acc[e] += xv.x*rw[(k+0)*NE+e] + xv.y*rw[(k+1)*NE+e]
                    + xv.z*rw[(k+2)*NE+e] + xv.w*rw[(k+3)*NE+e];
        }
    }
    #pragma unroll
    for (int off=16; off>0; off>>=1)
        #pragma unroll
        for (int e=0;e<NE;e++)
            acc[e] += __shfl_down_sync(0xFFFFFFFFu, acc[e], off);

    if (lane == 0){
        float p[NE];
        float m = -1e30f;
        #pragma unroll
        for (int e=0;e<NE;e++){ p[e] = acc[e] + rb[e]; m = fmaxf(m, p[e]); }
        float s = 0.0f;
        #pragma unroll
        for (int e=0;e<NE;e++){ p[e] = expf(p[e]-m); s += p[e]; }
        float inv_s = 1.0f/s;
        #pragma unroll
        for (int e=0;e<NE;e++){ p[e] *= inv_s; g_probs[t*NE+e] = p[e]; }

        int i0 = 0;
        #pragma unroll
        for (int e=1;e<NE;e++) if (p[e] > p[i0]) i0 = e;
        int i1 = (i0==0) ? 1 : 0;
        #pragma unroll
        for (int e=0;e<NE;e++) if (e != i0 && p[e] > p[i1]) i1 = e;

        float inv = 1.0f/(p[i0]+p[i1]);
        g_tok_e[t*2+0] = i0; g_tok_w[t*2+0] = p[i0]*inv;
        g_tok_e[t*2+1] = i1; g_tok_w[t*2+1] = p[i1]*inv;
        atomicAdd(&g_count[i0], 1);
        atomicAdd(&g_count[i1], 1);
    }
}

// -------- exclusive scan over 8 counts --------
__global__ void k_scan(){
    int s = 0;
    for (int e=0;e<NE;e++){ g_offset[e] = s; s += g_count[e]; g_count[e] = 0; }
    g_offset[NE] = s;
}

// -------- scatter assignments into expert-grouped lists --------
__global__ void k_scatter(){
    int i = blockIdx.x*blockDim.x + threadIdx.x;
    if (i >= NA) return;
    int e   = g_tok_e[i];
    int pos = g_offset[e] + atomicAdd(&g_count[e], 1);
    g_tok[pos] = i >> 1;
    g_wt[pos]  = g_tok_w[i];
}

// ===================== TF32 tensor-core grouped GEMM ========================
// Block tile 128x128, K-tile 32. 256 threads = 8 warps in 2x4.
// Warp tile 64x32 = 4x4 m16n8k8 mma tiles. A/B rounded to tf32 at smem fill.
#define ASTR 36    // As row stride (floats), [128][36]
#define BSTR 136   // Bs row stride (floats), [32][136]

__device__ __forceinline__ void mma_tf32(float* c, uint32_t a0, uint32_t a1,
                                         uint32_t a2, uint32_t a3,
                                         uint32_t b0, uint32_t b1){
    asm volatile(
        "mma.sync.aligned.m16n8k8.row.col.f32.tf32.tf32.f32 "
        "{%0,%1,%2,%3},{%4,%5,%6,%7},{%8,%9},{%0,%1,%2,%3};"
        : "+f"(c[0]), "+f"(c[1]), "+f"(c[2]), "+f"(c[3])
        : "r"(a0), "r"(a1), "r"(a2), "r"(a3), "r"(b0), "r"(b1));
}

// Core: compute C = Agather(128 rows, K) * B(K x 128 slice), then epilogue.
// MODE 0: GEMM1 (A = x gathered, B = w1, epilogue gelu -> g_h)
// MODE 1: GEMM2 (A = g_h rows (device symbol!), B = w2, epilogue atomic combine)
template<int MODE, int KDIM>
__global__ __launch_bounds__(256, 2)
void k_gemm_tc(const float* __restrict__ x_in,
               const float* __restrict__ W,
               const float* __restrict__ bias,
               float* __restrict__ out,
               int NSTRIDE /* row stride of W = N total */){
    const int e = blockIdx.z, mt = blockIdx.y, nt = blockIdx.x;
    const int off = g_offset[e];
    const int ne  = g_offset[e+1] - off;
    if (mt*128 >= ne) return;

    __shared__ float As[128*ASTR];
    __shared__ float Bs[32*BSTR];

    const int tid = threadIdx.x;
    const float* __restrict__ Bbase =
        W + (size_t)e*KDIM*NSTRIDE + nt*128;

    // A base: device-side symbol access for g_h (NEVER pass __device__ global
    // from host code — that passes the host shadow address).
    const float* __restrict__ Abase = (MODE == 0) ? x_in : (const float*)g_h;

    // ---- per-thread global-load mapping ----
    // A: 128 rows x 32 k = 1024 float4; thread j-th chunk: i = tid + 256*j
    const float* aptr[4];
    int arow[4];
    const int acol = (tid & 7) << 2;   // float offset within 32-k slab
    #pragma unroll
    for (int j=0;j<4;j++){
        int r = (tid + 256*j) >> 3;    // 0..127
        arow[j] = r;
        bool v = (mt*128 + r) < ne;
        if (MODE == 0){
            aptr[j] = v ? (Abase + (size_t)g_tok[off + mt*128 + r]*DM + acol)
                        : (const float*)0;
        } else {
            aptr[j] = v ? (Abase + (size_t)(off + mt*128 + r)*KDIM + acol)
                        : (const float*)0;
        }
    }
    // B: 32 k x 128 n = 1024 float4; i = tid + 256*j -> k = i>>5, nq = i&31
    int bkr[4], bnq[4];
    #pragma unroll
    for (int j=0;j<4;j++){
        int i = tid + 256*j;
        bkr[j] = i >> 5;
        bnq[j] = (i & 31) << 2;
    }

    const int lane = tid & 31, warp = tid >> 5;
    const int wr = warp >> 2, wc = warp & 3;   // 2 x 4 warps
    const int g = lane >> 2, tq = lane & 3;

    float acc[4][4][4];
    #pragma unroll
    for (int i=0;i<4;i++)
        #pragma unroll
        for (int j=0;j<4;j++)
            #pragma unroll
            for (int q=0;q<4;q++) acc[i][j][q] = 0.0f;

    for (int k0 = 0; k0 < KDIM; k0 += 32){
        // fill As (tf32-rounded)
        #pragma unroll
        for (int j=0;j<4;j++){
            float4 v = make_float4(0,0,0,0);
            if (aptr[j]) v = *(const float4*)(aptr[j] + k0);
            v.x = f2tf32(v.x); v.y = f2tf32(v.y);
            v.z = f2tf32(v.z); v.w = f2tf32(v.w);
            *(float4*)&As[arow[j]*ASTR + acol] = v;
        }
        // fill Bs (tf32-rounded)
        #pragma unroll
        for (int j=0;j<4;j++){
            float4 v = *(const float4*)(Bbase + (size_t)(k0 + bkr[j])*NSTRIDE + bnq[j]);
            v.x = f2tf32(v.x); v.y = f2tf32(v.y);
            v.z = f2tf32(v.z); v.w = f2tf32(v.w);
            *(float4*)&Bs[bkr[j]*BSTR + bnq[j]] = v;
        }
        __syncthreads();

        #pragma unroll
        for (int ks=0; ks<4; ks++){
            uint32_t a[4][4], b[4][2];
            #pragma unroll
            for (int mi=0; mi<4; mi++){
                int m = wr*64 + mi*16;
                a[mi][0] = __float_as_uint(As[(m+g  )*ASTR + ks*8 + tq    ]);
                a[mi][1] = __float_as_uint(As[(m+g+8)*ASTR + ks*8 + tq    ]);
                a[mi][2] = __float_as_uint(As[(m+g  )*ASTR + ks*8 + tq + 4]);
                a[mi][3] = __float_as_uint(As[(m+g+8)*ASTR + ks*8 + tq + 4]);
            }
            #pragma unroll
            for (int ni=0; ni<4; ni++){
                int n = wc*32 + ni*8;
                b[ni][0] = __float_as_uint(Bs[(ks*8 + tq    )*BSTR + n + g]);
                b[ni][1] = __float_as_uint(Bs[(ks*8 + tq + 4)*BSTR + n + g]);
            }
            #pragma unroll
            for (int mi=0; mi<4; mi++)
                #pragma unroll
                for (int ni=0; ni<4; ni++)
                    mma_tf32(acc[mi][ni], a[mi][0], a[mi][1], a[mi][2], a[mi][3],
                             b[ni][0], b[ni][1]);
        }
        __syncthreads();
    }

    // ---- epilogue ----
    #pragma unroll
    for (int mi=0; mi<4; mi++){
        #pragma unroll
        for (int half=0; half<2; half++){
            int m_local = wr*64 + mi*16 + g + half*8;
            if (mt*128 + m_local >= ne) continue;
            int grow = off + mt*128 + m_local;
            #pragma unroll
            for (int ni=0; ni<4; ni++){
                int n0 = nt*128 + wc*32 + ni*8 + tq*2;
                float v0 = acc[mi][ni][half*2+0];
                float v1 = acc[mi][ni][half*2+1];
                if (MODE == 0){
                    v0 += bias[e*FF + n0];
                    v1 += bias[e*FF + n0 + 1];
                    v0 = 0.5f*v0*(1.0f + erff(v0*0.70710678118654752440f));
                    v1 = 0.5f*v1*(1.0f + erff(v1*0.70710678118654752440f));
                    *(float2*)&g_h[(size_t)grow*FF + n0] = make_float2(v0, v1);
                } else {
                    int tok = g_tok[grow];
                    float wt = g_wt[grow];
                    v0 = wt*(v0 + bias[e*DM + n0]);
                    v1 = wt*(v1 + bias[e*DM + n0 + 1]);
                    atomicAdd(out + (size_t)tok*DM + n0,     v0);
                    atomicAdd(out + (size_t)tok*DM + n0 + 1, v1);
                }
            }
        }
    }
}

// -------- aux loss: var(mean_probs, ddof=1) --------
__global__ void k_aux(float* out, int out_size){
    __shared__ float red[256];
    __shared__ float meanp[NE];
    int tid = threadIdx.x;
    float s[NE];
    #pragma unroll
    for (int e=0;e<NE;e++) s[e]=0.0f;
    for (int t = tid; t < T_TOK; t += 256)
        #pragma unroll
        for (int e=0;e<NE;e++) s[e] += g_probs[t*NE+e];

    for (int e=0;e<NE;e++){
        red[tid] = s[e]; __syncthreads();
        for (int o=128;o>0;o>>=1){
            if (tid < o) red[tid] += red[tid+o];
            __syncthreads();
        }
        if (tid == 0) meanp[e] = red[0]/(float)T_TOK;
        __syncthreads();
    }
    if (tid == 0){
        float mu = 0.0f;
        #pragma unroll
        for (int e=0;e<NE;e++) mu += meanp[e];
        mu /= (float)NE;
        float v = 0.0f;
        #pragma unroll
        for (int e=0;e<NE;e++){ float d = meanp[e]-mu; v += d*d; }
        v /= (float)(NE-1);
        if (out_size > T_TOK*DM) out[T_TOK*DM] = v;
    }
}

extern "C" void kernel_launch(void* const* d_in, const int* in_sizes, int n_in,
                              void* d_out, int out_size){
    const float* x  = (const float*)d_in[0];
    const float* rw = (const float*)d_in[1];
    const float* rb = (const float*)d_in[2];
    const float* w1 = (const float*)d_in[3];
    const float* b1 = (const float*)d_in[4];
    const float* w2 = (const float*)d_in[5];
    const float* b2 = (const float*)d_in[6];
    float* out = (float*)d_out;

    k_zero   <<<1024, 256>>>(out);
    k_router <<<T_TOK/8, 256>>>(x, rw, rb);
    k_scan   <<<1, 1>>>();
    k_scatter<<<NA/256, 256>>>();
    // GEMM1: A = gathered x [*, DM], B = w1 [DM, FF] -> g_h (A base = x)
    k_gemm_tc<0, DM><<<dim3(FF/128, 64, NE), 256>>>(x, w1, b1, (float*)0, FF);
    // GEMM2: A = g_h (resolved device-side), B = w2 [FF, DM] -> out
    k_gemm_tc<1, FF><<<dim3(DM/128, 64, NE), 256>>>(x, w2, b2, out, DM);
    k_aux    <<<1, 256>>>(out, out_size);
}